// round 6
// baseline (speedup 1.0000x reference)
#include <cuda_runtime.h>
#include <math.h>

#define NB 64
#define NS 512
#define ND 1024
#define NH 1024
#define NK 4
#define DTC 0.05f

#define NCTA 128      // persistent CTAs (must all be co-resident)
#define GJ   32       // j-groups
#define BPC  16       // batches per CTA (64 / (NCTA/GJ))
#define JPC  32       // h-columns per CTA

// -------- device scratch (static allocation only; no cudaMalloc allowed) ----
__device__ float g_U[(size_t)NB * NS * NH];     // input projection, 128 MB
__device__ float g_hT[2 * NH * NB];             // double-buffered transposed h
__device__ float g_alpha[NB];
__device__ unsigned int g_count = 0;
__device__ unsigned int g_gen = 0;

// ---------------------------------------------------------------------------
// alpha[b] = exp(-dt / sum_k tau_k * softmax(complexity[b]*mw[k] + mb[k]))
// ---------------------------------------------------------------------------
__global__ void alpha_kernel(const float* __restrict__ comp,
                             const float* __restrict__ mw,
                             const float* __restrict__ mb,
                             const float* __restrict__ tau) {
    int b = threadIdx.x;
    if (b >= NB) return;
    float c = comp[b];
    float lg[NK];
    float mx = -1e30f;
#pragma unroll
    for (int k = 0; k < NK; k++) { lg[k] = c * mw[k] + mb[k]; mx = fmaxf(mx, lg[k]); }
    float se = 0.f;
#pragma unroll
    for (int k = 0; k < NK; k++) { lg[k] = expf(lg[k] - mx); se += lg[k]; }
    float mt = 0.f;
#pragma unroll
    for (int k = 0; k < NK; k++) mt += tau[k] * lg[k];
    mt /= se;
    g_alpha[b] = expf(-DTC / mt);
}

__global__ void zero_hT() {
    int i = blockIdx.x * blockDim.x + threadIdx.x;
    if (i < 2 * NH * NB) g_hT[i] = 0.f;
}

// ---------------------------------------------------------------------------
// U[m][n] = sum_k x[m][k] * W_in[n][k] + bias[n]
// M = B*S = 32768, N = H = 1024, K = D = 1024. 128x128 tile, Kt=8, 8x8/thread.
// ---------------------------------------------------------------------------
__global__ __launch_bounds__(256) void gemm_u(const float* __restrict__ A,
                                              const float* __restrict__ W,
                                              const float* __restrict__ bias) {
    __shared__ float As[8][128];
    __shared__ float Bs[8][128];
    int tid = threadIdx.x;
    int m0 = blockIdx.y * 128;
    int n0 = blockIdx.x * 128;

    int lr = tid >> 1;            // 0..127 (tile row)
    int lk = (tid & 1) * 4;       // 0 or 4
    const float* Ag = A + (size_t)(m0 + lr) * ND + lk;
    const float* Bg = W + (size_t)(n0 + lr) * ND + lk;

    int tx = tid & 15;            // n direction (8 cols each)
    int ty = tid >> 4;            // m direction (8 rows each)

    float acc[8][8];
#pragma unroll
    for (int i = 0; i < 8; i++)
#pragma unroll
        for (int j = 0; j < 8; j++) acc[i][j] = 0.f;

    for (int kt = 0; kt < ND; kt += 8) {
        float4 av = *(const float4*)(Ag + kt);
        float4 bv = *(const float4*)(Bg + kt);
        __syncthreads();
        As[lk + 0][lr] = av.x; As[lk + 1][lr] = av.y;
        As[lk + 2][lr] = av.z; As[lk + 3][lr] = av.w;
        Bs[lk + 0][lr] = bv.x; Bs[lk + 1][lr] = bv.y;
        Bs[lk + 2][lr] = bv.z; Bs[lk + 3][lr] = bv.w;
        __syncthreads();
#pragma unroll
        for (int k = 0; k < 8; k++) {
            float a[8], b[8];
            *(float4*)&a[0] = *(const float4*)&As[k][ty * 8];
            *(float4*)&a[4] = *(const float4*)&As[k][ty * 8 + 4];
            *(float4*)&b[0] = *(const float4*)&Bs[k][tx * 8];
            *(float4*)&b[4] = *(const float4*)&Bs[k][tx * 8 + 4];
#pragma unroll
            for (int i = 0; i < 8; i++)
#pragma unroll
                for (int j = 0; j < 8; j++)
                    acc[i][j] = fmaf(a[i], b[j], acc[i][j]);
        }
    }

    float bv0[8];
#pragma unroll
    for (int j = 0; j < 8; j++) bv0[j] = bias[n0 + tx * 8 + j];
#pragma unroll
    for (int i = 0; i < 8; i++) {
        float* Cp = g_U + (size_t)(m0 + ty * 8 + i) * NH + n0 + tx * 8;
        float4 v0 = make_float4(acc[i][0] + bv0[0], acc[i][1] + bv0[1],
                                acc[i][2] + bv0[2], acc[i][3] + bv0[3]);
        float4 v1 = make_float4(acc[i][4] + bv0[4], acc[i][5] + bv0[5],
                                acc[i][6] + bv0[6], acc[i][7] + bv0[7]);
        *(float4*)(Cp)     = v0;
        *(float4*)(Cp + 4) = v1;
    }
}

// ---------------------------------------------------------------------------
// Persistent recurrent kernel. 128 CTAs (4 batch-groups x 32 j-groups),
// 128 threads. W_rec slice transposed in SMEM, h double-buffered in L2
// (transposed layout), h-state in registers. One grid barrier per step.
// ---------------------------------------------------------------------------
__device__ __forceinline__ void grid_barrier() {
    __syncthreads();
    if (threadIdx.x == 0) {
        volatile unsigned int* genp = &g_gen;
        unsigned int g = *genp;
        __threadfence();                       // release this CTA's writes
        unsigned int a = atomicAdd(&g_count, 1u);
        if (a == NCTA - 1) {
            *(volatile unsigned int*)&g_count = 0;
            __threadfence();
            atomicAdd(&g_gen, 1u);             // release all
        } else {
            while (*genp == g) __nanosleep(64);
        }
    }
    __syncthreads();
}

__global__ __launch_bounds__(128, 1) void liquid_kernel(const float* __restrict__ Wr,
                                                        float* __restrict__ out) {
    extern __shared__ float smem[];
    float* Wt = smem;                  // [1024][32]  transposed W_rec slice (128 KB)
    float* hs = smem + 1024 * 32;      // [1024][16]  staged transposed h slice (64 KB)

    int cta = blockIdx.x;
    int jg = cta & (GJ - 1);
    int bg = cta >> 5;
    int j0 = jg * JPC;
    int b0 = bg * BPC;
    int tid = threadIdx.x;
    int tb = tid & 7;                  // batch-pair index   (8  -> 16 batches)
    int tj = tid >> 3;                 // column-pair index  (16 -> 32 columns)
    int bb = 2 * tb, jj = 2 * tj;

    // ---- one-time: load W_rec rows j0..j0+31, transposed into SMEM ----
    {
        int r  = tid >> 2;             // 0..31  (j within slice)
        int kq = (tid & 3) * 4;        // 0,4,8,12
        const float* wg = Wr + (size_t)(j0 + r) * NH + kq;
#pragma unroll 4
        for (int kk = 0; kk < NH; kk += 16) {
            float4 v = *(const float4*)(wg + kk);
            Wt[(kk + kq + 0) * 32 + r] = v.x;
            Wt[(kk + kq + 1) * 32 + r] = v.y;
            Wt[(kk + kq + 2) * 32 + r] = v.z;
            Wt[(kk + kq + 3) * 32 + r] = v.w;
        }
    }

    float a0 = g_alpha[b0 + bb];
    float a1 = g_alpha[b0 + bb + 1];
    float na0 = 1.f - a0, na1 = 1.f - a1;
    float h00 = 0.f, h01 = 0.f, h10 = 0.f, h11 = 0.f;
    __syncthreads();

    int bgl0 = b0 + bb;
    int jgl  = j0 + jj;
    size_t out_stride = (size_t)NS * NH;

    int sk = tid >> 2;                 // staging: k row
    int sc = (tid & 3) * 4;            // staging: 4-float column chunk

    for (int t = 0; t < NS; t++) {
        const float* rbuf = g_hT + (size_t)(t & 1) * NH * NB;        // read h_t
        float*       wbuf = g_hT + (size_t)((t + 1) & 1) * NH * NB;  // write h_{t+1}

        // ---- stage transposed h slice [1024][16] into SMEM (L2, bypass L1) ----
        {
            const float4* src = (const float4*)(rbuf + (size_t)sk * NB + b0 + sc);
            float4*       dst = (float4*)(hs + sk * 16 + sc);
#pragma unroll 8
            for (int kk = 0; kk < NH; kk += 32) {
                dst[kk * 4] = __ldcg(src + kk * 16);
            }
        }
        __syncthreads();

        // ---- 2x2 outer-product dot over k = 0..1023 ----
        float c00 = 0.f, c01 = 0.f, c10 = 0.f, c11 = 0.f;
        const float2* wp = (const float2*)(Wt + jj);
        const float2* hp = (const float2*)(hs + bb);
#pragma unroll 8
        for (int k = 0; k < NH; k++) {
            float2 wv = wp[k * 16];    // Wt[k][jj..jj+1]
            float2 hv = hp[k * 8];     // hs[k][bb..bb+1]
            c00 = fmaf(hv.x, wv.x, c00);
            c01 = fmaf(hv.x, wv.y, c01);
            c10 = fmaf(hv.y, wv.x, c10);
            c11 = fmaf(hv.y, wv.y, c11);
        }

        // ---- add u_t, activation, state update ----
        size_t ro0 = ((size_t)bgl0 * NS + t) * NH + jgl;
        size_t ro1 = ro0 + out_stride;
        float2 u0 = *(const float2*)(g_U + ro0);
        float2 u1 = *(const float2*)(g_U + ro1);
        h00 = a0 * h00 + na0 * tanhf(c00 + u0.x);
        h01 = a0 * h01 + na0 * tanhf(c01 + u0.y);
        h10 = a1 * h10 + na1 * tanhf(c10 + u1.x);
        h11 = a1 * h11 + na1 * tanhf(c11 + u1.y);

        // ---- write outputs (normal layout) + next-state (transposed, L2) ----
        *(float2*)(out + ro0) = make_float2(h00, h01);
        *(float2*)(out + ro1) = make_float2(h10, h11);
        __stcg((float2*)(wbuf + (size_t)jgl * NB + bgl0),       make_float2(h00, h10));
        __stcg((float2*)(wbuf + (size_t)(jgl + 1) * NB + bgl0), make_float2(h01, h11));

        grid_barrier();
    }

    // ---- h_final appended after output[B,S,H] ----
    float* hf = out + (size_t)NB * NS * NH;
    *(float2*)(hf + (size_t)bgl0 * NH + jgl)       = make_float2(h00, h01);
    *(float2*)(hf + (size_t)(bgl0 + 1) * NH + jgl) = make_float2(h10, h11);
}

// ---------------------------------------------------------------------------
extern "C" void kernel_launch(void* const* d_in, const int* in_sizes, int n_in,
                              void* d_out, int out_size) {
    const float* x    = (const float*)d_in[0];
    const float* comp = (const float*)d_in[1];
    const float* Wrec = (const float*)d_in[2];
    const float* Win  = (const float*)d_in[3];
    const float* bias = (const float*)d_in[4];
    const float* tau  = (const float*)d_in[5];
    const float* mw   = (const float*)d_in[6];
    const float* mb   = (const float*)d_in[7];
    float* out = (float*)d_out;

    const int smem_bytes = (1024 * 32 + 1024 * 16) * (int)sizeof(float);  // 196608
    cudaFuncSetAttribute(liquid_kernel, cudaFuncAttributeMaxDynamicSharedMemorySize,
                         smem_bytes);

    alpha_kernel<<<1, 64>>>(comp, mw, mb, tau);
    zero_hT<<<(2 * NH * NB + 1023) / 1024, 1024>>>();
    dim3 gemm_grid(NH / 128, (NB * NS) / 128);   // (8, 256)
    gemm_u<<<gemm_grid, 256>>>(x, Win, bias);
    liquid_kernel<<<NCTA, 128, smem_bytes>>>(Wrec, out);
}

// round 7
// speedup vs baseline: 1.4529x; 1.4529x over previous
#include <cuda_runtime.h>
#include <math.h>

#define NB 64
#define NS 512
#define ND 1024
#define NH 1024
#define NK 4
#define DTC 0.05f

#define NCTA 128      // persistent CTAs (1/SM, must all be co-resident)

typedef unsigned long long ull;

// ---------------- packed f32x2 helpers (FFMA2 — PTX only) -------------------
__device__ __forceinline__ ull fma2(ull a, ull b, ull c) {
    ull d;
    asm("fma.rn.f32x2 %0, %1, %2, %3;" : "=l"(d) : "l"(a), "l"(b), "l"(c));
    return d;
}
__device__ __forceinline__ ull pack2(float x, float y) {
    ull d;
    asm("mov.b64 %0, {%1, %2};" : "=l"(d) : "r"(__float_as_uint(x)), "r"(__float_as_uint(y)));
    return d;
}
__device__ __forceinline__ float2 unpack2(ull v) {
    unsigned int lo, hi;
    asm("mov.b64 {%0, %1}, %2;" : "=r"(lo), "=r"(hi) : "l"(v));
    return make_float2(__uint_as_float(lo), __uint_as_float(hi));
}

// -------- device scratch (static allocation only; no cudaMalloc allowed) ----
__device__ float g_U[(size_t)NB * NS * NH];     // input projection, 128 MB
__device__ float g_hT[2 * NH * NB];             // double-buffered transposed h
__device__ float g_alpha[NB];
__device__ unsigned int g_count = 0;
__device__ unsigned int g_gen = 0;

// ---------------------------------------------------------------------------
__global__ void alpha_kernel(const float* __restrict__ comp,
                             const float* __restrict__ mw,
                             const float* __restrict__ mb,
                             const float* __restrict__ tau) {
    int b = threadIdx.x;
    if (b >= NB) return;
    float c = comp[b];
    float lg[NK];
    float mx = -1e30f;
#pragma unroll
    for (int k = 0; k < NK; k++) { lg[k] = c * mw[k] + mb[k]; mx = fmaxf(mx, lg[k]); }
    float se = 0.f;
#pragma unroll
    for (int k = 0; k < NK; k++) { lg[k] = expf(lg[k] - mx); se += lg[k]; }
    float mt = 0.f;
#pragma unroll
    for (int k = 0; k < NK; k++) mt += tau[k] * lg[k];
    mt /= se;
    g_alpha[b] = expf(-DTC / mt);
}

__global__ void zero_hT() {
    int i = blockIdx.x * blockDim.x + threadIdx.x;
    if (i < 2 * NH * NB) g_hT[i] = 0.f;
}

// ---------------------------------------------------------------------------
// U[m][n] = sum_k x[m][k] * W_in[n][k] + bias[n]
// M = 32768, N = 1024, K = 1024. 128x128 tile, Kt=8, 8x8/thread via FFMA2
// (accumulators paired along n), register prefetch of next K-tile.
// ---------------------------------------------------------------------------
__global__ __launch_bounds__(256) void gemm_u(const float* __restrict__ A,
                                              const float* __restrict__ W,
                                              const float* __restrict__ bias) {
    __shared__ float As[8][128];
    __shared__ float Bs[8][128];
    int tid = threadIdx.x;
    int m0 = blockIdx.y * 128;
    int n0 = blockIdx.x * 128;

    int lr = tid >> 1;            // 0..127 (tile row)
    int lk = (tid & 1) * 4;       // 0 or 4
    const float* Ag = A + (size_t)(m0 + lr) * ND + lk;
    const float* Bg = W + (size_t)(n0 + lr) * ND + lk;

    int tx = tid & 15;            // n direction (8 cols each)
    int ty = tid >> 4;            // m direction (8 rows each)

    ull acc[8][4];
#pragma unroll
    for (int i = 0; i < 8; i++)
#pragma unroll
        for (int j = 0; j < 4; j++) acc[i][j] = 0ull;

    float4 av = *(const float4*)(Ag);
    float4 bv = *(const float4*)(Bg);

    for (int kt = 0; kt < ND; kt += 8) {
        __syncthreads();
        As[lk + 0][lr] = av.x; As[lk + 1][lr] = av.y;
        As[lk + 2][lr] = av.z; As[lk + 3][lr] = av.w;
        Bs[lk + 0][lr] = bv.x; Bs[lk + 1][lr] = bv.y;
        Bs[lk + 2][lr] = bv.z; Bs[lk + 3][lr] = bv.w;
        __syncthreads();
        if (kt + 8 < ND) {                       // prefetch next tile (overlaps compute)
            av = *(const float4*)(Ag + kt + 8);
            bv = *(const float4*)(Bg + kt + 8);
        }
#pragma unroll
        for (int k = 0; k < 8; k++) {
            float a[8];
            *(float4*)&a[0] = *(const float4*)&As[k][ty * 8];
            *(float4*)&a[4] = *(const float4*)&As[k][ty * 8 + 4];
            ulonglong2 b01 = *(const ulonglong2*)&Bs[k][tx * 8];
            ulonglong2 b23 = *(const ulonglong2*)&Bs[k][tx * 8 + 4];
            ull bb0 = b01.x, bb1 = b01.y, bb2 = b23.x, bb3 = b23.y;
#pragma unroll
            for (int i = 0; i < 8; i++) {
                ull ai = pack2(a[i], a[i]);
                acc[i][0] = fma2(ai, bb0, acc[i][0]);
                acc[i][1] = fma2(ai, bb1, acc[i][1]);
                acc[i][2] = fma2(ai, bb2, acc[i][2]);
                acc[i][3] = fma2(ai, bb3, acc[i][3]);
            }
        }
    }

    float bv0[8];
#pragma unroll
    for (int j = 0; j < 8; j++) bv0[j] = bias[n0 + tx * 8 + j];
#pragma unroll
    for (int i = 0; i < 8; i++) {
        float* Cp = g_U + (size_t)(m0 + ty * 8 + i) * NH + n0 + tx * 8;
        float2 c0 = unpack2(acc[i][0]);
        float2 c1 = unpack2(acc[i][1]);
        float2 c2 = unpack2(acc[i][2]);
        float2 c3 = unpack2(acc[i][3]);
        float4 v0 = make_float4(c0.x + bv0[0], c0.y + bv0[1], c1.x + bv0[2], c1.y + bv0[3]);
        float4 v1 = make_float4(c2.x + bv0[4], c2.y + bv0[5], c3.x + bv0[6], c3.y + bv0[7]);
        *(float4*)(Cp)     = v0;
        *(float4*)(Cp + 4) = v1;
    }
}

// ---------------------------------------------------------------------------
// Persistent recurrent kernel. 128 CTAs (32 j-groups x 4 batch-groups),
// 256 threads (8 warps = 8 k-slices of 128). Each CTA: 32 j x 16 b outputs.
// Per thread: 4j x 4b register tile over its warp's k-slice, FFMA2, then
// smem reduction over the 8 k-slices. W_rec slice (128 KB) resident in smem,
// transposed; h double-buffered in L2 (transposed), staged per-warp per-step.
// ---------------------------------------------------------------------------
__device__ __forceinline__ void grid_barrier() {
    __syncthreads();
    if (threadIdx.x == 0) {
        volatile unsigned int* genp = &g_gen;
        unsigned int g = *genp;
        __threadfence();                       // release this CTA's writes
        unsigned int a = atomicAdd(&g_count, 1u);
        if (a == NCTA - 1) {
            *(volatile unsigned int*)&g_count = 0;
            __threadfence();
            atomicAdd(&g_gen, 1u);             // release all
        } else {
            while (*genp == g) __nanosleep(32);
            __threadfence();                   // acquire
        }
    }
    __syncthreads();
}

__global__ __launch_bounds__(256, 1) void liquid_kernel(const float* __restrict__ Wr,
                                                        float* __restrict__ out) {
    extern __shared__ float smem[];
    float* Wt  = smem;                   // [1024][32]  W_rec^T slice, 128 KB
    float* hs  = smem + 1024 * 32;       // [1024][16]  staged h^T slice, 64 KB
    float* red = smem + 1024 * 48;       // [8][512]    k-slice partials, 16 KB

    int cta = blockIdx.x;
    int jg = cta & 31;                   // 32 j-groups
    int bg = cta >> 5;                   // 4 batch-groups
    int j0 = jg * 32;
    int b0 = bg * 16;
    int tid  = threadIdx.x;
    int w    = tid >> 5;                 // warp = k-slice (0..7)
    int lane = tid & 31;
    int tj = lane >> 2;                  // 0..7  -> j = j0 + 4*tj
    int tb = lane & 3;                   // 0..3  -> b = b0 + 4*tb
    int ks = w * 128;                    // this warp's k-slice start

    // ---- one-time: W_rec rows j0..j0+31, transposed into SMEM [k][j] ----
    {
        int r = tid & 31;                // j within slice
        int c = tid >> 5;                // 4-float k chunk selector
        const float* wg = Wr + (size_t)(j0 + r) * NH + c * 4;
#pragma unroll 4
        for (int kk = 0; kk < 32; kk++) {
            float4 v = *(const float4*)(wg + kk * 32);
            int kb = kk * 32 + c * 4;
            Wt[(kb + 0) * 32 + r] = v.x;
            Wt[(kb + 1) * 32 + r] = v.y;
            Wt[(kb + 2) * 32 + r] = v.z;
            Wt[(kb + 3) * 32 + r] = v.w;
        }
    }

    // ---- epilogue assignment: thread owns outputs o = 2*tid, 2*tid+1 ----
    int o  = 2 * tid;                    // 0..510
    int bl = o >> 5;                     // 0..15
    int jl = o & 31;                     // even
    int bo = b0 + bl;
    int jo = j0 + jl;
    float aa = g_alpha[bo];
    float na = 1.f - aa;
    float h0 = 0.f, h1 = 0.f;            // persistent h state in registers
    size_t orow = (size_t)bo * NS;       // out/U row base (in NH units)

    __syncthreads();

    int src_r = lane >> 2;               // staging row-within-8
    int src_c = lane & 3;                // staging float4 chunk

    for (int t = 0; t < NS; t++) {
        const float* rbuf = g_hT + (size_t)(t & 1) * NH * NB;
        float*       wbuf = g_hT + (size_t)((t + 1) & 1) * NH * NB;

        // ---- per-warp stage: own 128k x 16b h^T slice into SMEM (via L2) ----
        __syncwarp();
#pragma unroll
        for (int i = 0; i < 16; i++) {
            int row = ks + src_r + 8 * i;
            float4 v = __ldcg((const float4*)(rbuf + (size_t)row * NB + b0) + src_c);
            *((float4*)(hs + row * 16) + src_c) = v;
        }
        __syncwarp();

        // ---- 4j x 4b FFMA2 tile over this warp's 128-k slice ----
        ull c00 = 0, c01 = 0, c10 = 0, c11 = 0, c20 = 0, c21 = 0, c30 = 0, c31 = 0;
        const float* wp = Wt + ks * 32 + 4 * tj;
        const float* hp = hs + ks * 16 + 4 * tb;
#pragma unroll 8
        for (int k = 0; k < 128; k++) {
            ulonglong2 wv = *(const ulonglong2*)(wp + k * 32);   // 4 j values
            float4    hv  = *(const float4*)(hp + k * 16);       // 4 b values
            ull hb0 = pack2(hv.x, hv.x);
            ull hb1 = pack2(hv.y, hv.y);
            ull hb2 = pack2(hv.z, hv.z);
            ull hb3 = pack2(hv.w, hv.w);
            c00 = fma2(hb0, wv.x, c00); c01 = fma2(hb0, wv.y, c01);
            c10 = fma2(hb1, wv.x, c10); c11 = fma2(hb1, wv.y, c11);
            c20 = fma2(hb2, wv.x, c20); c21 = fma2(hb2, wv.y, c21);
            c30 = fma2(hb3, wv.x, c30); c31 = fma2(hb3, wv.y, c31);
        }

        // ---- store k-slice partials: red[w][ (4tb+bi)*32 + 4tj + 2jp ] ----
        {
            ull* rp = (ull*)(red + w * 512 + 4 * tb * 32 + 4 * tj);
            rp[0]      = c00; rp[1]      = c01;   // bi=0, jp=0/1
            rp[16]     = c10; rp[17]     = c11;   // bi=1 (+32 floats)
            rp[32]     = c20; rp[33]     = c21;   // bi=2
            rp[48]     = c30; rp[49]     = c31;   // bi=3
        }
        __syncthreads();

        // ---- reduce 8 slices, add u_t, tanh, state update, stores ----
        float2 s = make_float2(0.f, 0.f);
#pragma unroll
        for (int ww = 0; ww < 8; ww++) {
            float2 v = *(const float2*)(red + ww * 512 + o);
            s.x += v.x; s.y += v.y;
        }
        size_t ro = (orow + t) * NH + jo;
        float2 u = *(const float2*)(g_U + ro);
        h0 = aa * h0 + na * tanhf(s.x + u.x);
        h1 = aa * h1 + na * tanhf(s.y + u.y);
        *(float2*)(out + ro) = make_float2(h0, h1);
        __stcg(wbuf + (size_t)jo * NB + bo,       h0);
        __stcg(wbuf + (size_t)(jo + 1) * NB + bo, h1);

        grid_barrier();
    }

    // ---- h_final appended after output[B,S,H] ----
    float* hf = out + (size_t)NB * NS * NH;
    hf[(size_t)bo * NH + jo]     = h0;
    hf[(size_t)bo * NH + jo + 1] = h1;
}

// ---------------------------------------------------------------------------
extern "C" void kernel_launch(void* const* d_in, const int* in_sizes, int n_in,
                              void* d_out, int out_size) {
    const float* x    = (const float*)d_in[0];
    const float* comp = (const float*)d_in[1];
    const float* Wrec = (const float*)d_in[2];
    const float* Win  = (const float*)d_in[3];
    const float* bias = (const float*)d_in[4];
    const float* tau  = (const float*)d_in[5];
    const float* mw   = (const float*)d_in[6];
    const float* mb   = (const float*)d_in[7];
    float* out = (float*)d_out;

    const int smem_bytes = (1024 * 32 + 1024 * 16 + 8 * 512) * (int)sizeof(float); // 212992
    cudaFuncSetAttribute(liquid_kernel, cudaFuncAttributeMaxDynamicSharedMemorySize,
                         smem_bytes);

    alpha_kernel<<<1, 64>>>(comp, mw, mb, tau);
    zero_hT<<<(2 * NH * NB + 1023) / 1024, 1024>>>();
    dim3 gemm_grid(NH / 128, (NB * NS) / 128);   // (8, 256)
    gemm_u<<<gemm_grid, 256>>>(x, Win, bias);
    liquid_kernel<<<NCTA, 256, smem_bytes>>>(Wrec, out);
}